// round 12
// baseline (speedup 1.0000x reference)
#include <cuda_runtime.h>
#include <stdint.h>

// LayoutBBox: in (B,12,64) f32 -> out (B,8,128,128) f32
// out[b,c,h,w] = max_n xy[n,h,w]*cls[n,c], xy = max(lx(w)*gx(h), ly(h)*gy(w))
// prep: boxes SORTED by x1 (locality for warp-coherent visits), exact bitmasks
//       in sorted bit-order, pair-union row masks, packed records. PDL producer.
// main: 2 rows/thread (row pair), per-lane exact mask, divergent visit loop,
//       records staged in smem. Sorted order makes scattered LDS ~broadcast.

constexpr int Wd   = 128;
constexpr int Hd   = 128;
constexpr int NP   = Hd / 2;       // 64 row pairs
constexpr int NUMB = 64;
constexpr int NCLS = 8;
constexpr int INCH = 12;
constexpr int MAXB = 16;

using u64 = unsigned long long;

__device__ __forceinline__ u64 pk(float lo, float hi) {
    u64 r; asm("mov.b64 %0,{%1,%2};" : "=l"(r) : "f"(lo), "f"(hi)); return r;
}
__device__ __forceinline__ void upk(float& lo, float& hi, u64 v) {
    asm("mov.b64 {%0,%1},%2;" : "=f"(lo), "=f"(hi) : "l"(v));
}
__device__ __forceinline__ u64 pmul(u64 a, u64 b) {
    u64 r; asm("mul.rn.f32x2 %0,%1,%2;" : "=l"(r) : "l"(a), "l"(b)); return r;
}

__device__ ulonglong2 g_cmask[MAXB][Wd];    // (Mlx, Mgw) per (b,w), sorted bits
__device__ ulonglong2 g_rmask2[MAXB][NP];   // pair-union (Mgh, Mly), sorted bits
__device__ float4     g_p [MAXB][NUMB];     // sorted records: x1,x2,y1,y2
__device__ ulonglong2 g_ca[MAXB][NUMB];     // sorted packed (c0,c1),(c2,c3)
__device__ ulonglong2 g_cb[MAXB][NUMB];     // sorted packed (c4,c5),(c6,c7)

// rank of box tid under (x1, tid) lexicographic order — identical code path in
// both prep blocks so the permutation is bit-identical.
__device__ __forceinline__ int box_rank(const float* skey, int tid) {
    float key = skey[tid];
    int rank = 0;
    #pragma unroll 8
    for (int j = 0; j < NUMB; j++) {
        float kj = skey[j];
        rank += (kj < key) || (kj == key && j < tid);
    }
    return rank;
}

// ---------------- prep kernel: grid (2, B), block 1024 ----------------
__global__ void prep_kernel(const float* __restrict__ in)
{
    const int b   = blockIdx.y;
    const int tid = threadIdx.x;
    const float* base = in + (size_t)b * INCH * NUMB;

    __shared__ float  skey[NUMB];
    __shared__ int    sinv[NUMB];      // sorted slot -> original box
    __shared__ float2 ssrt[NUMB];      // sorted (x1,x2) or (y1,y2)

    // keys: x1 per original box (same arithmetic in both blocks)
    if (tid < NUMB) {
        float xc = base[0 * NUMB + tid] * 128.0f;
        float bw = base[2 * NUMB + tid] * 128.0f;
        skey[tid] = xc - 0.5f * bw;
    }
    __syncthreads();

    if (blockIdx.x == 0) {
        // ---- x-side: sorted records + column masks ----
        if (tid < NUMB) {
            int r = box_rank(skey, tid);
            sinv[r] = tid;
            float xc = base[0 * NUMB + tid] * 128.0f;
            float bw = base[2 * NUMB + tid] * 128.0f;
            ssrt[r] = make_float2(xc - 0.5f * bw, xc + 0.5f * bw);
        }
        __syncthreads();
        if (tid < NUMB) {                      // sorted slot tid
            int o = sinv[tid];
            float yc = base[1 * NUMB + o] * 128.0f;
            float bh = base[3 * NUMB + o] * 128.0f;
            float2 x = ssrt[tid];
            g_p[b][tid] = make_float4(x.x, x.y, yc - 0.5f * bh, yc + 0.5f * bh);
            ulonglong2 ca, cb;
            ca.x = pk(base[4 * NUMB + o],  base[5 * NUMB + o]);
            ca.y = pk(base[6 * NUMB + o],  base[7 * NUMB + o]);
            cb.x = pk(base[8 * NUMB + o],  base[9 * NUMB + o]);
            cb.y = pk(base[10 * NUMB + o], base[11 * NUMB + o]);
            g_ca[b][tid] = ca;
            g_cb[b][tid] = cb;
        }
        {   // column masks over sorted boxes, byte-parallel (1024 slots)
            int w = tid >> 3, j = tid & 7;
            float wf = (float)w;
            unsigned blx = 0, bgw = 0;
            #pragma unroll
            for (int k = 0; k < 8; k++) {
                float2 x = ssrt[8 * j + k];
                if (fabsf(wf - x.x) < 1.0f || fabsf(x.y - wf) < 1.0f) blx |= 1u << k;
                if (wf > x.x && wf < x.y)                             bgw |= 1u << k;
            }
            unsigned char* dst = (unsigned char*)&g_cmask[b][w];
            dst[j]     = (unsigned char)blx;
            dst[8 + j] = (unsigned char)bgw;
        }
    } else {
        // ---- y-side: pair-union row masks over sorted boxes ----
        if (tid < NUMB) {
            int r = box_rank(skey, tid);
            float yc = base[1 * NUMB + tid] * 128.0f;
            float bh = base[3 * NUMB + tid] * 128.0f;
            ssrt[r] = make_float2(yc - 0.5f * bh, yc + 0.5f * bh);
        }
        __syncthreads();
        if (tid < NP * 8) {                    // 512 slots
            int p = tid >> 3, j = tid & 7;
            float hf0 = (float)(2 * p);
            float hf1 = hf0 + 1.0f;
            unsigned bgh = 0, bly = 0;
            #pragma unroll
            for (int k = 0; k < 8; k++) {
                float2 y = ssrt[8 * j + k];
                bool g0 = (hf0 > y.x && hf0 < y.y);
                bool g1 = (hf1 > y.x && hf1 < y.y);
                if (g0 || g1) bgh |= 1u << k;
                bool l0 = (fabsf(hf0 - y.x) < 1.0f || fabsf(y.y - hf0) < 1.0f);
                bool l1 = (fabsf(hf1 - y.x) < 1.0f || fabsf(y.y - hf1) < 1.0f);
                if (l0 || l1) bly |= 1u << k;
            }
            unsigned char* dst = (unsigned char*)&g_rmask2[b][p];
            dst[j]     = (unsigned char)bgh;
            dst[8 + j] = (unsigned char)bly;
        }
    }
    asm volatile("griddepcontrol.launch_dependents;" ::: "memory");
}

// -------- main kernel: grid (NP/2, B), block (128, 2); one row-pair/thread ----
__global__ __launch_bounds__(256)
void layout_bbox_main(float* __restrict__ out)
{
    __shared__ float4     sp [NUMB];
    __shared__ ulonglong2 sca[NUMB];
    __shared__ ulonglong2 scb[NUMB];

    const int tx  = threadIdx.x;                      // w
    const int ty  = threadIdx.y;
    const int tid = ty * Wd + tx;
    const int b   = blockIdx.y;
    const int p   = blockIdx.x + ty * (NP / 2);       // interleaved pair index
    const int h0  = 2 * p;
    const float wf  = (float)tx;
    const float hf0 = (float)h0;
    const float hf1 = hf0 + 1.0f;

    asm volatile("griddepcontrol.wait;" ::: "memory");

    // parallel staging: 192 threads, one record-piece each
    if (tid < NUMB)                sp [tid]            = g_p [b][tid];
    else if (tid < 2 * NUMB)       sca[tid - NUMB]     = g_ca[b][tid - NUMB];
    else if (tid < 3 * NUMB)       scb[tid - 2 * NUMB] = g_cb[b][tid - 2 * NUMB];

    const ulonglong2 cm  = g_cmask[b][tx];
    const ulonglong2 rmu = g_rmask2[b][p];
    u64 m = (cm.x & rmu.x) | (cm.y & rmu.y);          // exact pair-union set

    __syncthreads();

    float a0 = 0.f, a1 = 0.f, a2 = 0.f, a3 = 0.f;
    float a4 = 0.f, a5 = 0.f, a6 = 0.f, a7 = 0.f;
    float b0 = 0.f, b1 = 0.f, b2 = 0.f, b3 = 0.f;
    float b4 = 0.f, b5 = 0.f, b6 = 0.f, b7 = 0.f;

    while (m) {                                       // divergent per-lane loop
        int n = __ffsll((long long)m) - 1;
        m &= m - 1;
        float4 pbox = sp[n];                          // LDS.128, near-broadcast

        // column profile — shared by both rows
        float dx1 = wf - pbox.x, dx2 = pbox.y - wf;
        float lx = fmaxf(0.0f, fmaxf(1.0f - fabsf(dx1), 1.0f - fabsf(dx2)));
        float gy = __saturatef(dx1) * __saturatef(dx2);

        float dy1 = hf0 - pbox.z, dy2 = pbox.w - hf0;
        float gx = __saturatef(dy1) * __saturatef(dy2);
        float ly = fmaxf(0.0f, fmaxf(1.0f - fabsf(dy1), 1.0f - fabsf(dy2)));
        float xy0 = fmaxf(lx * gx, ly * gy);

        dy1 = hf1 - pbox.z; dy2 = pbox.w - hf1;
        gx = __saturatef(dy1) * __saturatef(dy2);
        ly = fmaxf(0.0f, fmaxf(1.0f - fabsf(dy1), 1.0f - fabsf(dy2)));
        float xy1 = fmaxf(lx * gx, ly * gy);

        u64 x0 = pk(xy0, xy0);
        u64 x1 = pk(xy1, xy1);
        ulonglong2 ca = sca[n];                       // LDS.128
        ulonglong2 cb = scb[n];                       // LDS.128
        float p0, p1;
        upk(p0, p1, pmul(x0, ca.x)); a0 = fmaxf(a0, p0); a1 = fmaxf(a1, p1);
        upk(p0, p1, pmul(x0, ca.y)); a2 = fmaxf(a2, p0); a3 = fmaxf(a3, p1);
        upk(p0, p1, pmul(x0, cb.x)); a4 = fmaxf(a4, p0); a5 = fmaxf(a5, p1);
        upk(p0, p1, pmul(x0, cb.y)); a6 = fmaxf(a6, p0); a7 = fmaxf(a7, p1);
        upk(p0, p1, pmul(x1, ca.x)); b0 = fmaxf(b0, p0); b1 = fmaxf(b1, p1);
        upk(p0, p1, pmul(x1, ca.y)); b2 = fmaxf(b2, p0); b3 = fmaxf(b3, p1);
        upk(p0, p1, pmul(x1, cb.x)); b4 = fmaxf(b4, p0); b5 = fmaxf(b5, p1);
        upk(p0, p1, pmul(x1, cb.y)); b6 = fmaxf(b6, p0); b7 = fmaxf(b7, p1);
    }

    float* o = out + (((size_t)b * NCLS) * Hd + h0) * Wd + tx;
    const int cs = Hd * Wd;
    o[0 * cs] = a0; o[1 * cs] = a1; o[2 * cs] = a2; o[3 * cs] = a3;
    o[4 * cs] = a4; o[5 * cs] = a5; o[6 * cs] = a6; o[7 * cs] = a7;
    o += Wd;
    o[0 * cs] = b0; o[1 * cs] = b1; o[2 * cs] = b2; o[3 * cs] = b3;
    o[4 * cs] = b4; o[5 * cs] = b5; o[6 * cs] = b6; o[7 * cs] = b7;
}

extern "C" void kernel_launch(void* const* d_in, const int* in_sizes, int n_in,
                              void* d_out, int out_size)
{
    const float* in = (const float*)d_in[0];
    float* out = (float*)d_out;
    int B = in_sizes[0] / (INCH * NUMB);   // 16

    prep_kernel<<<dim3(2, B), 1024>>>(in);

    cudaLaunchConfig_t cfg = {};
    cfg.gridDim  = dim3(NP / 2, B);        // (32, B) = 512 CTAs
    cfg.blockDim = dim3(Wd, 2);            // 128 x 2 = 256 threads
    cudaLaunchAttribute attr[1];
    attr[0].id = cudaLaunchAttributeProgrammaticStreamSerialization;
    attr[0].val.programmaticStreamSerializationAllowed = 1;
    cfg.attrs = attr;
    cfg.numAttrs = 1;
    cudaLaunchKernelEx(&cfg, layout_bbox_main, out);
}

// round 13
// speedup vs baseline: 1.0592x; 1.0592x over previous
#include <cuda_runtime.h>
#include <stdint.h>

// LayoutBBox: in (B,12,64) f32 -> out (B,8,128,128) f32
// out[b,c,h,w] = max_n xy[n,h,w]*cls[n,c], xy = max(lx(w)*gx(h), ly(h)*gy(w))
// prep: exact per-(b,w) column masks, pair-union row masks, packed records.
// main: 2 rows/thread (row pair), per-lane exact mask, divergent visit loop;
//       row profiles (gx,ly) for the CTA's two pairs PRECOMPUTED into smem in
//       the prologue -> per-trip row math collapses to one LDS.128 + 2 pmul.

constexpr int Wd   = 128;
constexpr int Hd   = 128;
constexpr int NP   = Hd / 2;       // 64 row pairs
constexpr int NUMB = 64;
constexpr int NCLS = 8;
constexpr int INCH = 12;
constexpr int MAXB = 16;

using u64 = unsigned long long;

__device__ __forceinline__ u64 pk(float lo, float hi) {
    u64 r; asm("mov.b64 %0,{%1,%2};" : "=l"(r) : "f"(lo), "f"(hi)); return r;
}
__device__ __forceinline__ void upk(float& lo, float& hi, u64 v) {
    asm("mov.b64 {%0,%1},%2;" : "=f"(lo), "=f"(hi) : "l"(v));
}
__device__ __forceinline__ u64 pmul(u64 a, u64 b) {
    u64 r; asm("mul.rn.f32x2 %0,%1,%2;" : "=l"(r) : "l"(a), "l"(b)); return r;
}

__device__ ulonglong2 g_cmask[MAXB][Wd];    // (Mlx, Mgw) per (b,w)
__device__ ulonglong2 g_rmask2[MAXB][NP];   // pair-union (Mgh, Mly)
__device__ float4     g_p [MAXB][NUMB];     // x1, x2, y1, y2
__device__ ulonglong2 g_ca[MAXB][NUMB];     // packed (c0,c1),(c2,c3)
__device__ ulonglong2 g_cb[MAXB][NUMB];     // packed (c4,c5),(c6,c7)

// ---------------- prep kernel: grid (2, B), block 1024 ----------------
__global__ void prep_kernel(const float* __restrict__ in)
{
    const int b   = blockIdx.y;
    const int tid = threadIdx.x;
    const float* base = in + (size_t)b * INCH * NUMB;

    if (blockIdx.x == 0) {
        // records + column masks
        if (tid < NUMB) {
            float xc = base[0 * NUMB + tid] * 128.0f;
            float yc = base[1 * NUMB + tid] * 128.0f;
            float bw = base[2 * NUMB + tid] * 128.0f;
            float bh = base[3 * NUMB + tid] * 128.0f;
            g_p[b][tid] = make_float4(xc - 0.5f * bw, xc + 0.5f * bw,
                                      yc - 0.5f * bh, yc + 0.5f * bh);
            ulonglong2 ca, cb;
            ca.x = pk(base[4 * NUMB + tid],  base[5 * NUMB + tid]);
            ca.y = pk(base[6 * NUMB + tid],  base[7 * NUMB + tid]);
            cb.x = pk(base[8 * NUMB + tid],  base[9 * NUMB + tid]);
            cb.y = pk(base[10 * NUMB + tid], base[11 * NUMB + tid]);
            g_ca[b][tid] = ca;
            g_cb[b][tid] = cb;
        }
        {   // column masks, byte-parallel (1024 slots)
            int w = tid >> 3, j = tid & 7;
            float wf = (float)w;
            unsigned blx = 0, bgw = 0;
            #pragma unroll
            for (int k = 0; k < 8; k++) {
                int n = 8 * j + k;
                float xc = base[0 * NUMB + n] * 128.0f;
                float bw = base[2 * NUMB + n] * 128.0f;
                float x1 = xc - 0.5f * bw, x2 = xc + 0.5f * bw;
                if (fabsf(wf - x1) < 1.0f || fabsf(x2 - wf) < 1.0f) blx |= 1u << k;
                if (wf > x1 && wf < x2)                             bgw |= 1u << k;
            }
            unsigned char* dst = (unsigned char*)&g_cmask[b][w];
            dst[j]     = (unsigned char)blx;
            dst[8 + j] = (unsigned char)bgw;
        }
    } else {
        // pair-union row masks (512 slots)
        if (tid < NP * 8) {
            int p = tid >> 3, j = tid & 7;
            float hf0 = (float)(2 * p);
            float hf1 = hf0 + 1.0f;
            unsigned bgh = 0, bly = 0;
            #pragma unroll
            for (int k = 0; k < 8; k++) {
                int n = 8 * j + k;
                float yc = base[1 * NUMB + n] * 128.0f;
                float bh = base[3 * NUMB + n] * 128.0f;
                float y1 = yc - 0.5f * bh, y2 = yc + 0.5f * bh;
                bool g0 = (hf0 > y1 && hf0 < y2);
                bool g1 = (hf1 > y1 && hf1 < y2);
                if (g0 || g1) bgh |= 1u << k;
                bool l0 = (fabsf(hf0 - y1) < 1.0f || fabsf(y2 - hf0) < 1.0f);
                bool l1 = (fabsf(hf1 - y1) < 1.0f || fabsf(y2 - hf1) < 1.0f);
                if (l0 || l1) bly |= 1u << k;
            }
            unsigned char* dst = (unsigned char*)&g_rmask2[b][p];
            dst[j]     = (unsigned char)bgh;
            dst[8 + j] = (unsigned char)bly;
        }
    }
    asm volatile("griddepcontrol.launch_dependents;" ::: "memory");
}

// -------- main kernel: grid (NP/2, B), block (128, 2); one row-pair/thread ----
__global__ __launch_bounds__(256)
void layout_bbox_main(float* __restrict__ out)
{
    __shared__ float2     sspx[NUMB];         // (x1, x2)
    __shared__ ulonglong2 sht2[2 * NUMB];     // [local pair][n]: (gx0,ly0),(gx1,ly1)
    __shared__ ulonglong2 sca [NUMB];
    __shared__ ulonglong2 scb [NUMB];

    const int tx  = threadIdx.x;                      // w
    const int ty  = threadIdx.y;
    const int tid = ty * Wd + tx;
    const int b   = blockIdx.y;
    const int p   = blockIdx.x + ty * (NP / 2);       // interleaved pair index
    const int h0  = 2 * p;
    const float wf = (float)tx;

    asm volatile("griddepcontrol.wait;" ::: "memory");

    // ---- prologue staging ----
    if (tid < NUMB) {                                 // (x1,x2) for column math
        float4 q = g_p[b][tid];
        sspx[tid] = make_float2(q.x, q.y);
    } else if (tid < 2 * NUMB) {
        sca[tid - NUMB] = g_ca[b][tid - NUMB];
    } else if (tid < 3 * NUMB) {
        scb[tid - 2 * NUMB] = g_cb[b][tid - 2 * NUMB];
    }
    // row-profile table for the CTA's two pairs (workers 128..255)
    if (tid >= 128) {
        int wkr   = tid - 128;                        // 0..127
        int local = wkr >> 6;                         // 0,1
        int n     = wkr & 63;
        int pw    = blockIdx.x + local * (NP / 2);
        float hf0 = (float)(2 * pw);
        float hf1 = hf0 + 1.0f;
        float4 q  = g_p[b][n];                        // need .z, .w
        float dy1 = hf0 - q.z, dy2 = q.w - hf0;
        float gx0 = __saturatef(dy1) * __saturatef(dy2);
        float ly0 = fmaxf(0.0f, fmaxf(1.0f - fabsf(dy1), 1.0f - fabsf(dy2)));
        dy1 = hf1 - q.z; dy2 = q.w - hf1;
        float gx1 = __saturatef(dy1) * __saturatef(dy2);
        float ly1 = fmaxf(0.0f, fmaxf(1.0f - fabsf(dy1), 1.0f - fabsf(dy2)));
        ulonglong2 e;
        e.x = pk(gx0, ly0);
        e.y = pk(gx1, ly1);
        sht2[local * NUMB + n] = e;
    }

    const ulonglong2 cm  = g_cmask[b][tx];
    const ulonglong2 rmu = g_rmask2[b][p];
    u64 m = (cm.x & rmu.x) | (cm.y & rmu.y);          // exact pair-union set

    __syncthreads();

    const ulonglong2* __restrict__ ht = sht2 + ty * NUMB;

    float a0 = 0.f, a1 = 0.f, a2 = 0.f, a3 = 0.f;
    float a4 = 0.f, a5 = 0.f, a6 = 0.f, a7 = 0.f;
    float b0 = 0.f, b1 = 0.f, b2 = 0.f, b3 = 0.f;
    float b4 = 0.f, b5 = 0.f, b6 = 0.f, b7 = 0.f;

    while (m) {                                       // divergent per-lane loop
        int n = __ffsll((long long)m) - 1;
        m &= m - 1;

        float2 xb = sspx[n];                          // LDS.64
        float dx1 = wf - xb.x, dx2 = xb.y - wf;
        float lx = fmaxf(0.0f, fmaxf(1.0f - fabsf(dx1), 1.0f - fabsf(dx2)));
        float gy = __saturatef(dx1) * __saturatef(dx2);
        u64 wv = pk(lx, gy);

        ulonglong2 hv = ht[n];                        // LDS.128: (gx,ly) both rows
        float t0, t1;
        upk(t0, t1, pmul(wv, hv.x));                  // (lx*gx0, gy*ly0)
        float xy0 = fmaxf(t0, t1);
        upk(t0, t1, pmul(wv, hv.y));
        float xy1 = fmaxf(t0, t1);

        u64 x0 = pk(xy0, xy0);
        u64 x1 = pk(xy1, xy1);
        ulonglong2 ca = sca[n];                       // LDS.128
        ulonglong2 cb = scb[n];                       // LDS.128
        float p0, p1;
        upk(p0, p1, pmul(x0, ca.x)); a0 = fmaxf(a0, p0); a1 = fmaxf(a1, p1);
        upk(p0, p1, pmul(x0, ca.y)); a2 = fmaxf(a2, p0); a3 = fmaxf(a3, p1);
        upk(p0, p1, pmul(x0, cb.x)); a4 = fmaxf(a4, p0); a5 = fmaxf(a5, p1);
        upk(p0, p1, pmul(x0, cb.y)); a6 = fmaxf(a6, p0); a7 = fmaxf(a7, p1);
        upk(p0, p1, pmul(x1, ca.x)); b0 = fmaxf(b0, p0); b1 = fmaxf(b1, p1);
        upk(p0, p1, pmul(x1, ca.y)); b2 = fmaxf(b2, p0); b3 = fmaxf(b3, p1);
        upk(p0, p1, pmul(x1, cb.x)); b4 = fmaxf(b4, p0); b5 = fmaxf(b5, p1);
        upk(p0, p1, pmul(x1, cb.y)); b6 = fmaxf(b6, p0); b7 = fmaxf(b7, p1);
    }

    float* o = out + (((size_t)b * NCLS) * Hd + h0) * Wd + tx;
    const int cs = Hd * Wd;
    o[0 * cs] = a0; o[1 * cs] = a1; o[2 * cs] = a2; o[3 * cs] = a3;
    o[4 * cs] = a4; o[5 * cs] = a5; o[6 * cs] = a6; o[7 * cs] = a7;
    o += Wd;
    o[0 * cs] = b0; o[1 * cs] = b1; o[2 * cs] = b2; o[3 * cs] = b3;
    o[4 * cs] = b4; o[5 * cs] = b5; o[6 * cs] = b6; o[7 * cs] = b7;
}

extern "C" void kernel_launch(void* const* d_in, const int* in_sizes, int n_in,
                              void* d_out, int out_size)
{
    const float* in = (const float*)d_in[0];
    float* out = (float*)d_out;
    int B = in_sizes[0] / (INCH * NUMB);   // 16

    prep_kernel<<<dim3(2, B), 1024>>>(in);

    cudaLaunchConfig_t cfg = {};
    cfg.gridDim  = dim3(NP / 2, B);        // (32, B) = 512 CTAs
    cfg.blockDim = dim3(Wd, 2);            // 128 x 2 = 256 threads
    cudaLaunchAttribute attr[1];
    attr[0].id = cudaLaunchAttributeProgrammaticStreamSerialization;
    attr[0].val.programmaticStreamSerializationAllowed = 1;
    cfg.attrs = attr;
    cfg.numAttrs = 1;
    cudaLaunchKernelEx(&cfg, layout_bbox_main, out);
}